// round 3
// baseline (speedup 1.0000x reference)
#include <cuda_runtime.h>

#define B_   512
#define F_   512
#define NK   50
#define DK   16
#define NCOL (NK * DK)     // 800
#define OUTW (F_ + NK)     // 562

// Scratch: act transposed to [k][b][d] layout, split into two K-halves
// (summed at read time; avoids fp32 atomics in the GEMM).
__device__ float g_act0[B_ * NCOL];
__device__ float g_act1[B_ * NCOL];

// ---------------------------------------------------------------------------
// Kernel 0: copy x into out[:, 0:512] and zero the features region
// (d_out is poisoned 0xAA; pairwise kernel accumulates with atomicAdd).
// ---------------------------------------------------------------------------
__global__ void init_kernel(const float* __restrict__ x, float* __restrict__ out) {
    int i = blockIdx.x * blockDim.x + threadIdx.x;
    if (i < B_ * OUTW) {
        int b = i / OUTW;
        int j = i - b * OUTW;
        out[i] = (j < F_) ? x[b * F_ + j] : 0.0f;
    }
}

// ---------------------------------------------------------------------------
// Kernel 1: fp32 SIMT GEMM  act[b, n] = sum_k x[b,k] * W[k,n]
// Tile 32(M) x 64(N) x 16(K), 128 threads, 4x4 micro-tile.
// blockIdx.z selects K-half (0..255 -> g_act0, 256..511 -> g_act1).
// Output written transposed: dst[(n>>4)*B_*DK + m*DK + (n&15)].
// ---------------------------------------------------------------------------
#define BM 32
#define BN 64
#define BK 16

__global__ __launch_bounds__(128) void gemm_kernel(const float* __restrict__ A,
                                                   const float* __restrict__ Wm) {
    __shared__ float As[BK][BM + 4];   // row stride 36 floats (16B-aligned rows)
    __shared__ float Bs[BK][BN];

    const int tid = threadIdx.x;
    const int tx = tid & 15;           // 0..15 -> 4 cols each
    const int ty = tid >> 4;           // 0..7  -> 4 rows each
    const int n0 = blockIdx.x * BN;
    const int m0 = blockIdx.y * BM;
    const int kbase = blockIdx.z * 256;
    float* __restrict__ dst = blockIdx.z ? g_act1 : g_act0;

    // A-load mapping: each thread loads one float4 (row = tid>>2, colgrp = tid&3)
    const int arow = tid >> 2;            // 0..31
    const int acol = (tid & 3) << 2;      // 0,4,8,12
    // B-load mapping: two float4 per thread (rows tid>>4 and tid>>4 + 8)
    const int brow = tid >> 4;            // 0..7
    const int bn   = n0 + ((tid & 15) << 2);

    float acc[4][4];
#pragma unroll
    for (int i = 0; i < 4; i++)
#pragma unroll
        for (int j = 0; j < 4; j++) acc[i][j] = 0.0f;

    for (int kt = 0; kt < 256; kt += BK) {
        const int k0 = kbase + kt;

        // Load A tile (transposed into As[k][m])
        float4 av = *(const float4*)&A[(m0 + arow) * F_ + k0 + acol];
        As[acol + 0][arow] = av.x;
        As[acol + 1][arow] = av.y;
        As[acol + 2][arow] = av.z;
        As[acol + 3][arow] = av.w;

        // Load B tile (guard the partial last N-tile: 768..831 vs NCOL=800)
        float4 b0 = make_float4(0.f, 0.f, 0.f, 0.f);
        float4 b1 = make_float4(0.f, 0.f, 0.f, 0.f);
        if (bn < NCOL) {
            b0 = *(const float4*)&Wm[(k0 + brow) * NCOL + bn];
            b1 = *(const float4*)&Wm[(k0 + brow + 8) * NCOL + bn];
        }
        *(float4*)&Bs[brow][tx << 2]     = b0;
        *(float4*)&Bs[brow + 8][tx << 2] = b1;

        __syncthreads();

#pragma unroll
        for (int kk = 0; kk < BK; kk++) {
            float4 a = *(const float4*)&As[kk][ty << 2];
            float4 b = *(const float4*)&Bs[kk][tx << 2];
            acc[0][0] += a.x * b.x; acc[0][1] += a.x * b.y; acc[0][2] += a.x * b.z; acc[0][3] += a.x * b.w;
            acc[1][0] += a.y * b.x; acc[1][1] += a.y * b.y; acc[1][2] += a.y * b.z; acc[1][3] += a.y * b.w;
            acc[2][0] += a.z * b.x; acc[2][1] += a.z * b.y; acc[2][2] += a.z * b.z; acc[2][3] += a.z * b.w;
            acc[3][0] += a.w * b.x; acc[3][1] += a.w * b.y; acc[3][2] += a.w * b.z; acc[3][3] += a.w * b.w;
        }
        __syncthreads();
    }

    // Store: cols n = n0 + tx*4 .. +3 all live in one kernel-slab (n&15 in {0,4,8,12})
    const int n = n0 + (tx << 2);
    if (n < NCOL) {
        const int kk = n >> 4;
        const int d  = n & 15;
#pragma unroll
        for (int i = 0; i < 4; i++) {
            const int m = m0 + (ty << 2) + i;
            float4 v = make_float4(acc[i][0], acc[i][1], acc[i][2], acc[i][3]);
            *(float4*)&dst[kk * (B_ * DK) + m * DK + d] = v;
        }
    }
}

// ---------------------------------------------------------------------------
// Kernel 2: pairwise L1 + exp, packed f32x2 math.
// grid = (NK, 4 b-chunks of 128, 2 b2-halves of 256), 128 threads.
// SMEM holds 256 act rows (16 floats each) for kernel k. Registers hold the
// NEGATED own row packed as 8 x u64, so diff = packed add; abs = AND mask
// (2x LOP3, alu pipe) overlapping the fma-pipe packed adds.
// ---------------------------------------------------------------------------
__device__ __forceinline__ unsigned long long f2add(unsigned long long a,
                                                    unsigned long long b) {
    unsigned long long r;
    asm("add.rn.f32x2 %0, %1, %2;" : "=l"(r) : "l"(a), "l"(b));
    return r;
}

__global__ __launch_bounds__(128) void pairwise_kernel(float* __restrict__ out) {
    const int k     = blockIdx.x;   // 0..49
    const int chunk = blockIdx.y;   // 0..3
    const int half  = blockIdx.z;   // 0..1

    __shared__ float sbuf[256 * DK];   // 16 KB

    const float* __restrict__ base0 = g_act0 + k * (B_ * DK);
    const float* __restrict__ base1 = g_act1 + k * (B_ * DK);
    const int b2base = half * 256;

    // Stage 256 rows (sum of the two K-half partials) into SMEM
    {
        const float4* s0 = (const float4*)(base0 + b2base * DK);
        const float4* s1 = (const float4*)(base1 + b2base * DK);
        float4* d4 = (float4*)sbuf;
#pragma unroll
        for (int i = threadIdx.x; i < 256 * DK / 4; i += 128) {
            float4 v0 = s0[i];
            float4 v1 = s1[i];
            v0.x += v1.x; v0.y += v1.y; v0.z += v1.z; v0.w += v1.w;
            d4[i] = v0;
        }
    }

    // Own row, negated and packed into 8 u64 (f32x2 lanes {lo=2j, hi=2j+1})
    const int b = chunk * 128 + threadIdx.x;
    unsigned long long an[8];
    {
        const float* a0 = base0 + b * DK;
        const float* a1 = base1 + b * DK;
#pragma unroll
        for (int j = 0; j < 8; j++) {
            float f0 = a0[2 * j]     + a1[2 * j];
            float f1 = a0[2 * j + 1] + a1[2 * j + 1];
            unsigned long long p = ((unsigned long long)__float_as_uint(f1) << 32)
                                 | (unsigned long long)__float_as_uint(f0);
            an[j] = p ^ 0x8000000080000000ull;   // negate both lanes
        }
    }
    __syncthreads();

    const unsigned long long MASK = 0x7fffffff7fffffffull;
    float fsum = 0.0f;

#pragma unroll 2
    for (int b2 = 0; b2 < 256; b2++) {
        const ulonglong2* sp = ((const ulonglong2*)sbuf) + (b2 << 2);
        ulonglong2 q0 = sp[0];   // broadcast LDS.128, conflict-free
        ulonglong2 q1 = sp[1];
        ulonglong2 q2 = sp[2];
        ulonglong2 q3 = sp[3];

        unsigned long long m0 = f2add(q0.x, an[0]) & MASK;
        unsigned long long m1 = f2add(q0.y, an[1]) & MASK;
        unsigned long long m2 = f2add(q1.x, an[2]) & MASK;
        unsigned long long m3 = f2add(q1.y, an[3]) & MASK;
        unsigned long long m4 = f2add(q2.x, an[4]) & MASK;
        unsigned long long m5 = f2add(q2.y, an[5]) & MASK;
        unsigned long long m6 = f2add(q3.x, an[6]) & MASK;
        unsigned long long m7 = f2add(q3.y, an[7]) & MASK;

        unsigned long long t0 = f2add(m0, m1);
        unsigned long long t1 = f2add(m2, m3);
        unsigned long long t2 = f2add(m4, m5);
        unsigned long long t3 = f2add(m6, m7);
        t0 = f2add(t0, t1);
        t2 = f2add(t2, t3);
        t0 = f2add(t0, t2);

        float lo = __uint_as_float((unsigned int)t0);
        float hi = __uint_as_float((unsigned int)(t0 >> 32));
        float l1 = lo + hi;

        fsum += __expf(-l1);
    }

    atomicAdd(&out[b * OUTW + F_ + k], fsum);
}

// ---------------------------------------------------------------------------
extern "C" void kernel_launch(void* const* d_in, const int* in_sizes, int n_in,
                              void* d_out, int out_size) {
    const float* x = (const float*)d_in[0];
    const float* W = (const float*)d_in[1];
    // Defensive: identify by element count (x = 512*512, W = 512*800)
    if (n_in >= 2 && in_sizes[0] == F_ * NCOL && in_sizes[1] == B_ * F_) {
        const float* t = x; x = W; W = t;
    }
    float* out = (float*)d_out;

    init_kernel<<<(B_ * OUTW + 255) / 256, 256>>>(x, out);
    gemm_kernel<<<dim3((NCOL + BN - 1) / BN, B_ / BM, 2), 128>>>(x, W);
    pairwise_kernel<<<dim3(NK, 4, 2), 128>>>(out);
}

// round 4
// speedup vs baseline: 1.1699x; 1.1699x over previous
#include <cuda_runtime.h>
#include <cstdint>

#define B_   512
#define F_   512
#define NK   50
#define DK   16
#define NCOL (NK * DK)     // 800
#define OUTW (F_ + NK)     // 562

// act in [k][b][d] layout (single buffer: each GEMM CTA owns its full K reduction)
__device__ float g_act[B_ * NCOL];

// ---------------------------------------------------------------------------
// Kernel 1: tf32 tensor-core GEMM  act[b, n] = sum_k x[b,k] * W[k,n]
// CTA tile 64(M) x 64(N) x 32(K-slab), 128 threads = 4 warps (2x2),
// warp tile 32x32 = 2(m16) x 4(n8) mma.sync.m16n8k8 tiles, 64 k-steps.
// Prologue also initializes out[:, :512] = x and out[:, 512:] = 0
// (replaces the separate init launch; pairwise runs after and atomically adds).
// ---------------------------------------------------------------------------
__global__ __launch_bounds__(128) void gemm_kernel(const float* __restrict__ x,
                                                   const float* __restrict__ Wm,
                                                   float* __restrict__ out) {
    // ---- fused init of the output buffer (grid-stride) ----
    {
        int gtid = blockIdx.x * 128 + blockIdx.y * (13 * 128) + threadIdx.x;
        const int nthreads = 13 * 8 * 128;
        for (int i = gtid; i < B_ * OUTW; i += nthreads) {
            int b = i / OUTW;
            int j = i - b * OUTW;
            out[i] = (j < F_) ? x[b * F_ + j] : 0.0f;
        }
    }

    __shared__ float As[32][72];   // [k][cm] permuted-m columns, stride 72 (==8 mod 32)
    __shared__ float Bs[32][72];   // [k][n],  stride 72

    const int tid  = threadIdx.x;
    const int warp = tid >> 5;
    const int lane = tid & 31;
    const int gid  = lane >> 2;    // 0..7
    const int tig  = lane & 3;     // 0..3
    const int wm   = warp & 1;     // warp row   (2 x 32 rows)
    const int wn   = warp >> 1;    // warp col   (2 x 32 cols)

    const int n0 = blockIdx.x * 64;
    const int m0 = blockIdx.y * 64;

    // staging maps
    const int a_row = tid >> 1;                 // 0..63  (m within tile)
    const int a_k0  = (tid & 1) << 4;           // 0 or 16 (k within slab)
    const int a_mt  = a_row >> 4;
    const int a_r   = a_row & 15;
    const int a_cm  = (a_mt << 4) + ((a_r & 7) << 1) + (a_r >> 3);   // paired-row perm

    const int b_kk  = tid >> 2;                 // 0..31
    const int b_c0  = (tid & 3) << 2;           // 0,4,8,12  (+16*i)

    float acc[2][4][4];
#pragma unroll
    for (int mt = 0; mt < 2; mt++)
#pragma unroll
        for (int nt = 0; nt < 4; nt++)
#pragma unroll
            for (int j = 0; j < 4; j++) acc[mt][nt][j] = 0.0f;

    float4 pa[4], pb[4];

    // prefetch slab 0
    {
        const float* xa = &x[(m0 + a_row) * F_ + a_k0];
#pragma unroll
        for (int i = 0; i < 4; i++) pa[i] = *(const float4*)&xa[4 * i];
#pragma unroll
        for (int i = 0; i < 4; i++) {
            int c = b_c0 + 16 * i;
            pb[i] = (n0 + c < NCOL) ? *(const float4*)&Wm[b_kk * NCOL + n0 + c]
                                    : make_float4(0.f, 0.f, 0.f, 0.f);
        }
    }

    for (int s = 0; s < 16; s++) {
        // commit prefetched slab to SMEM
#pragma unroll
        for (int i = 0; i < 4; i++) {
            As[a_k0 + 4 * i + 0][a_cm] = pa[i].x;
            As[a_k0 + 4 * i + 1][a_cm] = pa[i].y;
            As[a_k0 + 4 * i + 2][a_cm] = pa[i].z;
            As[a_k0 + 4 * i + 3][a_cm] = pa[i].w;
            *(float4*)&Bs[b_kk][b_c0 + 16 * i] = pb[i];
        }
        __syncthreads();

        // prefetch next slab while computing this one
        if (s < 15) {
            const int k0 = (s + 1) * 32;
            const float* xa = &x[(m0 + a_row) * F_ + k0 + a_k0];
#pragma unroll
            for (int i = 0; i < 4; i++) pa[i] = *(const float4*)&xa[4 * i];
#pragma unroll
            for (int i = 0; i < 4; i++) {
                int c = b_c0 + 16 * i;
                pb[i] = (n0 + c < NCOL)
                      ? *(const float4*)&Wm[(k0 + b_kk) * NCOL + n0 + c]
                      : make_float4(0.f, 0.f, 0.f, 0.f);
            }
        }

#pragma unroll
        for (int ks = 0; ks < 4; ks++) {
            const int kr = ks * 8 + tig;
            // A fragments: paired-row layout -> LDS.64 gives (a0,a1) / (a2,a3)
            uint32_t afr[2][4];
#pragma unroll
            for (int mt = 0; mt < 2; mt++) {
                const int col = ((wm * 2 + mt) << 4) + (gid << 1);
                float2 p01 = *(const float2*)&As[kr][col];
                float2 p23 = *(const float2*)&As[kr + 4][col];
                afr[mt][0] = __float_as_uint(p01.x);
                afr[mt][1] = __float_as_uint(p01.y);
                afr[mt][2] = __float_as_uint(p23.x);
                afr[mt][3] = __float_as_uint(p23.y);
            }
            uint32_t bfr[4][2];
#pragma unroll
            for (int nt = 0; nt < 4; nt++) {
                const int col = wn * 32 + nt * 8 + gid;
                bfr[nt][0] = __float_as_uint(Bs[kr][col]);
                bfr[nt][1] = __float_as_uint(Bs[kr + 4][col]);
            }
#pragma unroll
            for (int mt = 0; mt < 2; mt++)
#pragma unroll
                for (int nt = 0; nt < 4; nt++) {
                    asm volatile(
                        "mma.sync.aligned.m16n8k8.row.col.f32.tf32.tf32.f32 "
                        "{%0,%1,%2,%3}, {%4,%5,%6,%7}, {%8,%9}, {%0,%1,%2,%3};"
                        : "+f"(acc[mt][nt][0]), "+f"(acc[mt][nt][1]),
                          "+f"(acc[mt][nt][2]), "+f"(acc[mt][nt][3])
                        : "r"(afr[mt][0]), "r"(afr[mt][1]),
                          "r"(afr[mt][2]), "r"(afr[mt][3]),
                          "r"(bfr[nt][0]), "r"(bfr[nt][1]));
                }
        }
        __syncthreads();
    }

    // epilogue: store transposed into g_act[k][b][d]
#pragma unroll
    for (int mt = 0; mt < 2; mt++) {
        const int br = m0 + wm * 32 + mt * 16 + gid;
#pragma unroll
        for (int nt = 0; nt < 4; nt++) {
            const int n = n0 + wn * 32 + nt * 8 + 2 * tig;
            if (n < NCOL) {
                const int kk = n >> 4;
                const int d  = n & 15;
                *(float2*)&g_act[kk * (B_ * DK) + br * DK + d] =
                    make_float2(acc[mt][nt][0], acc[mt][nt][1]);
                *(float2*)&g_act[kk * (B_ * DK) + (br + 8) * DK + d] =
                    make_float2(acc[mt][nt][2], acc[mt][nt][3]);
            }
        }
    }
}

// ---------------------------------------------------------------------------
// Kernel 2: pairwise L1 + exp, packed f32x2 math (unchanged core).
// grid = (NK, 4 b-chunks of 128, 2 b2-halves of 256), 128 threads.
// ---------------------------------------------------------------------------
__device__ __forceinline__ unsigned long long f2add(unsigned long long a,
                                                    unsigned long long b) {
    unsigned long long r;
    asm("add.rn.f32x2 %0, %1, %2;" : "=l"(r) : "l"(a), "l"(b));
    return r;
}

__global__ __launch_bounds__(128) void pairwise_kernel(float* __restrict__ out) {
    const int k     = blockIdx.x;   // 0..49
    const int chunk = blockIdx.y;   // 0..3
    const int half  = blockIdx.z;   // 0..1

    __shared__ float sbuf[256 * DK];   // 16 KB

    const float* __restrict__ base = g_act + k * (B_ * DK);
    const int b2base = half * 256;

    // Stage 256 rows into SMEM
    {
        const float4* s4 = (const float4*)(base + b2base * DK);
        float4* d4 = (float4*)sbuf;
#pragma unroll
        for (int i = threadIdx.x; i < 256 * DK / 4; i += 128) d4[i] = s4[i];
    }

    // Own row, negated and packed into 8 u64 (f32x2 lanes {lo=2j, hi=2j+1})
    const int b = chunk * 128 + threadIdx.x;
    unsigned long long an[8];
    {
        const float* a0 = base + b * DK;
#pragma unroll
        for (int j = 0; j < 8; j++) {
            unsigned long long p =
                ((unsigned long long)__float_as_uint(a0[2 * j + 1]) << 32)
                | (unsigned long long)__float_as_uint(a0[2 * j]);
            an[j] = p ^ 0x8000000080000000ull;   // negate both lanes
        }
    }
    __syncthreads();

    const unsigned long long MASK = 0x7fffffff7fffffffull;
    float fsum = 0.0f;

#pragma unroll 4
    for (int b2 = 0; b2 < 256; b2++) {
        const ulonglong2* sp = ((const ulonglong2*)sbuf) + (b2 << 2);
        ulonglong2 q0 = sp[0];   // broadcast LDS.128, conflict-free
        ulonglong2 q1 = sp[1];
        ulonglong2 q2 = sp[2];
        ulonglong2 q3 = sp[3];

        unsigned long long m0 = f2add(q0.x, an[0]) & MASK;
        unsigned long long m1 = f2add(q0.y, an[1]) & MASK;
        unsigned long long m2 = f2add(q1.x, an[2]) & MASK;
        unsigned long long m3 = f2add(q1.y, an[3]) & MASK;
        unsigned long long m4 = f2add(q2.x, an[4]) & MASK;
        unsigned long long m5 = f2add(q2.y, an[5]) & MASK;
        unsigned long long m6 = f2add(q3.x, an[6]) & MASK;
        unsigned long long m7 = f2add(q3.y, an[7]) & MASK;

        unsigned long long t0 = f2add(m0, m1);
        unsigned long long t1 = f2add(m2, m3);
        unsigned long long t2 = f2add(m4, m5);
        unsigned long long t3 = f2add(m6, m7);
        t0 = f2add(t0, t1);
        t2 = f2add(t2, t3);
        t0 = f2add(t0, t2);

        float lo = __uint_as_float((unsigned int)t0);
        float hi = __uint_as_float((unsigned int)(t0 >> 32));
        float l1 = lo + hi;

        fsum += __expf(-l1);
    }

    atomicAdd(&out[b * OUTW + F_ + k], fsum);
}

// ---------------------------------------------------------------------------
extern "C" void kernel_launch(void* const* d_in, const int* in_sizes, int n_in,
                              void* d_out, int out_size) {
    const float* x = (const float*)d_in[0];
    const float* W = (const float*)d_in[1];
    // Defensive: identify by element count (x = 512*512, W = 512*800)
    if (n_in >= 2 && in_sizes[0] == F_ * NCOL && in_sizes[1] == B_ * F_) {
        const float* t = x; x = W; W = t;
    }
    float* out = (float*)d_out;

    gemm_kernel<<<dim3(13, 8), 128>>>(x, W, out);
    pairwise_kernel<<<dim3(NK, 4, 2), 128>>>(out);
}